// round 11
// baseline (speedup 1.0000x reference)
#include <cuda_runtime.h>

#define Bc   2
#define Lc   512
#define DIMc 128
#define Kc   32
#define EPSc 1e-5f
#define RPB  4      // rows per block in the GEMV kernel
#define FTI  16     // fuse: i-rows per block (two per warp)
#define FTJ  32     // fuse: j-rows per block (smem tile)

// Scratch: 6 x 512KB = 3MB, L2-resident.
__device__ float g_out_mean[Bc * Lc * DIMc];
__device__ float g_in_mean [Bc * Lc * DIMc];
__device__ float g_out_agg [Bc * Lc * DIMc];
__device__ float g_in_agg  [Bc * Lc * DIMc];
__device__ float g_go      [Bc * Lc * DIMc];  // out_agg @ Wg_o + b_g
__device__ float g_gi      [Bc * Lc * DIMc];  // in_agg  @ Wg_i

__device__ __forceinline__ float tanh_approx(float x) {
    float r;
    asm("tanh.approx.f32 %0, %1;" : "=f"(r) : "f"(x));
    return r;
}

// ---------------------------------------------------------------------------
// Kernel 1: gather-means. One block per global row (b*L + r), 256 threads:
// d = t&127, h = t>>7 (k-half). 32 independent DRAM loads per thread.
// ---------------------------------------------------------------------------
__global__ void __launch_bounds__(256) means_kernel(const float* __restrict__ pair)
{
    __shared__ float sm[2][2][DIMc];   // [arr][h][d]
    const int rr = blockIdx.x;         // b*L + r
    const int b  = rr >> 9;
    const int rl = rr & (Lc - 1);
    const int t  = threadIdx.x;
    const int d  = t & 127;
    const int h  = t >> 7;

    float so = 0.f, si = 0.f;
    #pragma unroll
    for (int kk = 0; kk < Kc / 2; kk++) {
        const int k   = h * (Kc / 2) + kk;
        const int idx = (k * (Lc - 1)) / (Kc - 1);   // exact floor(linspace)
        so += pair[((size_t)rr * Lc + idx) * DIMc + d];             // [b,r,idx,d]
        si += pair[(((size_t)b * Lc + idx) * Lc + rl) * DIMc + d];  // [b,idx,r,d]
    }
    sm[0][h][d] = so;
    sm[1][h][d] = si;
    __syncthreads();
    if (h == 0) {
        g_out_mean[rr * DIMc + d] = (sm[0][0][d] + sm[0][1][d]) * (1.f / Kc);
        g_in_mean [rr * DIMc + d] = (sm[1][0][d] + sm[1][1][d]) * (1.f / Kc);
    }
}

// ---------------------------------------------------------------------------
// Kernel 2: agg GEMVs + gate GEMVs chained through smem.
// 256 threads: d = t&127, h = t>>7 selects (oa,W_out)|(ia,W_in) then (go)|(gi).
// ---------------------------------------------------------------------------
__global__ void __launch_bounds__(256) agg_gate_kernel(
    const float* __restrict__ W_out, const float* __restrict__ b_out,
    const float* __restrict__ W_in,  const float* __restrict__ b_in,
    const float* __restrict__ W_g,   const float* __restrict__ b_g)
{
    __shared__ float s_om[RPB][DIMc];
    __shared__ float s_im[RPB][DIMc];
    __shared__ float s_a [2][RPB][DIMc];   // [0]=oa, [1]=ia

    const int t  = threadIdx.x;
    const int d  = t & 127;
    const int h  = t >> 7;
    const int r0 = blockIdx.x * RPB;

    for (int s = t; s < RPB * DIMc; s += 256) {
        const int r = s >> 7, dd = s & 127;
        s_om[r][dd] = g_out_mean[(r0 + r) * DIMc + dd];
        s_im[r][dd] = g_in_mean [(r0 + r) * DIMc + dd];
    }
    __syncthreads();

    // agg GEMVs
    {
        const float* __restrict__ W = h ? W_in : W_out;
        const float (*src)[DIMc]    = h ? s_im : s_om;
        float* __restrict__ dst     = h ? g_in_agg : g_out_agg;
        float acc[RPB];
        const float bv = h ? b_in[d] : b_out[d];
        #pragma unroll
        for (int r = 0; r < RPB; r++) acc[r] = bv;
        #pragma unroll 8
        for (int m = 0; m < DIMc; m++) {
            const float w = W[m * DIMc + d];
            #pragma unroll
            for (int r = 0; r < RPB; r++)
                acc[r] = fmaf(src[r][m], w, acc[r]);
        }
        #pragma unroll
        for (int r = 0; r < RPB; r++) {
            dst[(r0 + r) * DIMc + d] = acc[r];
            s_a[h][r][d] = acc[r];
        }
    }
    __syncthreads();

    // gate GEMVs: go = oa@Wg_o + b_g ; gi = ia@Wg_i
    {
        const float* __restrict__ W = W_g + h * DIMc * DIMc;
        float* __restrict__ dst     = h ? g_gi : g_go;
        float acc[RPB];
        const float bv = h ? 0.f : b_g[d];
        #pragma unroll
        for (int r = 0; r < RPB; r++) acc[r] = bv;
        #pragma unroll 8
        for (int m = 0; m < DIMc; m++) {
            const float w = W[m * DIMc + d];
            #pragma unroll
            for (int r = 0; r < RPB; r++)
                acc[r] = fmaf(s_a[h][r][m], w, acc[r]);
        }
        #pragma unroll
        for (int r = 0; r < RPB; r++)
            dst[(r0 + r) * DIMc + d] = acc[r];
    }
}

// ---------------------------------------------------------------------------
// Kernel 3: fused gate/blend + LayerNorm.
// 16 lanes per row (8 floats/lane). Warp owns TWO i-rows (oa/go in regs),
// so each smem read of j-data (ia/gi) is reused across 2 rows:
// per-row L1 cost = 4 LDG + 4 STG + 4 LDS + 4 SHFL wavefronts.
// ---------------------------------------------------------------------------
__device__ __forceinline__ void blend4(
    const float4 p, const float4 OA, const float4 IA,
    const float4 GO, const float4 GI, float* x)
{
    float z, g, u;
    z = GO.x + GI.x; g = fmaf(0.5f, tanh_approx(0.5f * z), 0.5f);
    u = OA.x + IA.x; x[0] = fmaf(g, u - p.x, p.x);
    z = GO.y + GI.y; g = fmaf(0.5f, tanh_approx(0.5f * z), 0.5f);
    u = OA.y + IA.y; x[1] = fmaf(g, u - p.y, p.y);
    z = GO.z + GI.z; g = fmaf(0.5f, tanh_approx(0.5f * z), 0.5f);
    u = OA.z + IA.z; x[2] = fmaf(g, u - p.z, p.z);
    z = GO.w + GI.w; g = fmaf(0.5f, tanh_approx(0.5f * z), 0.5f);
    u = OA.w + IA.w; x[3] = fmaf(g, u - p.w, p.w);
}

__device__ __forceinline__ void ln_write(
    const float* x, const float4 lw0, const float4 lw1,
    const float4 lb0, const float4 lb1, float4* dst)
{
    float s = 0.f, sq = 0.f;
    #pragma unroll
    for (int e = 0; e < 8; e++) { s += x[e]; sq = fmaf(x[e], x[e], sq); }
    #pragma unroll
    for (int o = 8; o; o >>= 1) {
        s  += __shfl_xor_sync(0xFFFFFFFFu, s,  o);
        sq += __shfl_xor_sync(0xFFFFFFFFu, sq, o);
    }
    const float mean = s * (1.f / DIMc);
    const float rstd = rsqrtf(sq * (1.f / DIMc) - mean * mean + EPSc);
    float4 o0, o1;
    o0.x = fmaf((x[0] - mean) * rstd, lw0.x, lb0.x);
    o0.y = fmaf((x[1] - mean) * rstd, lw0.y, lb0.y);
    o0.z = fmaf((x[2] - mean) * rstd, lw0.z, lb0.z);
    o0.w = fmaf((x[3] - mean) * rstd, lw0.w, lb0.w);
    o1.x = fmaf((x[4] - mean) * rstd, lw1.x, lb1.x);
    o1.y = fmaf((x[5] - mean) * rstd, lw1.y, lb1.y);
    o1.z = fmaf((x[6] - mean) * rstd, lw1.z, lb1.z);
    o1.w = fmaf((x[7] - mean) * rstd, lw1.w, lb1.w);
    __stcs(&dst[0], o0);
    __stcs(&dst[1], o1);
}

__global__ void __launch_bounds__(256) fuse_ln_kernel(
    const float* __restrict__ pair,
    const float* __restrict__ ln_w,
    const float* __restrict__ ln_b,
    float* __restrict__ out)
{
    __shared__ float s_ia[FTJ][DIMc];
    __shared__ float s_gi[FTJ][DIMc];

    const int t    = threadIdx.x;
    const int tile = blockIdx.x;             // b*(32*16) + it*16 + jt
    const int b    = tile >> 9;
    const int it   = (tile >> 4) & 31;
    const int jt   = tile & 15;
    const int i0   = it * FTI, j0 = jt * FTJ;

    const float4* __restrict__ ia4 = (const float4*)g_in_agg;
    const float4* __restrict__ gi4 = (const float4*)g_gi;

    #pragma unroll
    for (int s = t; s < FTJ * 32; s += 256) {
        const int row = s >> 5, c = s & 31;
        ((float4*)s_ia[row])[c] = ia4[(b * Lc + j0 + row) * 32 + c];
        ((float4*)s_gi[row])[c] = gi4[(b * Lc + j0 + row) * 32 + c];
    }
    __syncthreads();

    const int warp = t >> 5;
    const int lane = t & 31;
    const int grp  = lane >> 4;   // which j of the pair this lane serves
    const int lr   = lane & 15;   // 16-lane position within a row (8 floats)
    const int biA  = b * Lc + i0 + warp * 2;      // first i-row of this warp
    const int biB  = biA + 1;

    const float4* __restrict__ oa4 = (const float4*)g_out_agg;
    const float4* __restrict__ go4 = (const float4*)g_go;
    const float4 oaA0 = oa4[biA * 32 + lr * 2];
    const float4 oaA1 = oa4[biA * 32 + lr * 2 + 1];
    const float4 goA0 = go4[biA * 32 + lr * 2];
    const float4 goA1 = go4[biA * 32 + lr * 2 + 1];
    const float4 oaB0 = oa4[biB * 32 + lr * 2];
    const float4 oaB1 = oa4[biB * 32 + lr * 2 + 1];
    const float4 goB0 = go4[biB * 32 + lr * 2];
    const float4 goB1 = go4[biB * 32 + lr * 2 + 1];
    const float4 lw0 = ((const float4*)ln_w)[lr * 2];
    const float4 lw1 = ((const float4*)ln_w)[lr * 2 + 1];
    const float4 lb0 = ((const float4*)ln_b)[lr * 2];
    const float4 lb1 = ((const float4*)ln_b)[lr * 2 + 1];

    const float4* __restrict__ p4 = (const float4*)pair;
    float4* __restrict__ o4p = (float4*)out;
    const size_t baseA = ((size_t)biA * Lc + j0) * 32 + lr * 2;
    const size_t baseB = ((size_t)biB * Lc + j0) * 32 + lr * 2;

    #pragma unroll 1
    for (int jj = 0; jj < FTJ; jj += 2) {
        const int j = jj + grp;               // lanes 0-15: jj, lanes 16-31: jj+1
        const size_t offA = baseA + (size_t)j * 32;
        const size_t offB = baseB + (size_t)j * 32;

        // front-batch all global loads + smem j-data (reused for both i-rows)
        const float4 pA0 = __ldcs(&p4[offA]);
        const float4 pA1 = __ldcs(&p4[offA + 1]);
        const float4 pB0 = __ldcs(&p4[offB]);
        const float4 pB1 = __ldcs(&p4[offB + 1]);
        const float4 ia0 = ((const float4*)s_ia[j])[lr * 2];
        const float4 ia1 = ((const float4*)s_ia[j])[lr * 2 + 1];
        const float4 gi0 = ((const float4*)s_gi[j])[lr * 2];
        const float4 gi1 = ((const float4*)s_gi[j])[lr * 2 + 1];

        float xA[8], xB[8];
        blend4(pA0, oaA0, ia0, goA0, gi0, xA);
        blend4(pA1, oaA1, ia1, goA1, gi1, xA + 4);
        blend4(pB0, oaB0, ia0, goB0, gi0, xB);
        blend4(pB1, oaB1, ia1, goB1, gi1, xB + 4);

        ln_write(xA, lw0, lw1, lb0, lb1, &o4p[offA]);
        ln_write(xB, lw0, lw1, lb0, lb1, &o4p[offB]);
    }
}

extern "C" void kernel_launch(void* const* d_in, const int* in_sizes, int n_in,
                              void* d_out, int out_size) {
    const float* pair  = (const float*)d_in[0];
    const float* W_out = (const float*)d_in[1];
    const float* b_out = (const float*)d_in[2];
    const float* W_in  = (const float*)d_in[3];
    const float* b_in  = (const float*)d_in[4];
    const float* W_g   = (const float*)d_in[5];
    const float* b_g   = (const float*)d_in[6];
    const float* ln_w  = (const float*)d_in[7];
    const float* ln_b  = (const float*)d_in[8];
    float* out = (float*)d_out;

    means_kernel<<<Bc * Lc, 256>>>(pair);
    agg_gate_kernel<<<(Bc * Lc) / RPB, 256>>>(W_out, b_out, W_in, b_in, W_g, b_g);
    fuse_ln_kernel<<<Bc * (Lc / FTI) * (Lc / FTJ), 256>>>(pair, ln_w, ln_b, out);
}

// round 13
// speedup vs baseline: 1.0638x; 1.0638x over previous
#include <cuda_runtime.h>
#include <cuda_fp16.h>

#define Bc   2
#define Lc   512
#define DIMc 128
#define Kc   32
#define EPSc 1e-5f
#define RPB  4      // rows per block in the GEMV kernel
#define FTI  8      // fuse: i-rows per block (one per warp)  [R7 config]
#define FTJ  32     // fuse: j-rows per block (smem tile)

// Scratch: 6 x 512KB = 3MB, L2-resident.
__device__ float g_out_mean[Bc * Lc * DIMc];
__device__ float g_in_mean [Bc * Lc * DIMc];
__device__ float g_out_agg [Bc * Lc * DIMc];
__device__ float g_in_agg  [Bc * Lc * DIMc];
__device__ float g_go      [Bc * Lc * DIMc];  // out_agg @ Wg_o + b_g
__device__ float g_gi      [Bc * Lc * DIMc];  // in_agg  @ Wg_i

__device__ __forceinline__ float tanh_approx(float x) {
    float r;
    asm("tanh.approx.f32 %0, %1;" : "=f"(r) : "f"(x));
    return r;
}

// ---------------------------------------------------------------------------
// Kernel 1: gather-means. One block per global row (b*L + r), 256 threads:
// d = t&127, h = t>>7 (k-half). 32 independent DRAM loads per thread.
// ---------------------------------------------------------------------------
__global__ void __launch_bounds__(256) means_kernel(const float* __restrict__ pair)
{
    __shared__ float sm[2][2][DIMc];   // [arr][h][d]
    const int rr = blockIdx.x;         // b*L + r
    const int b  = rr >> 9;
    const int rl = rr & (Lc - 1);
    const int t  = threadIdx.x;
    const int d  = t & 127;
    const int h  = t >> 7;

    float so = 0.f, si = 0.f;
    #pragma unroll
    for (int kk = 0; kk < Kc / 2; kk++) {
        const int k   = h * (Kc / 2) + kk;
        const int idx = (k * (Lc - 1)) / (Kc - 1);   // exact floor(linspace)
        so += pair[((size_t)rr * Lc + idx) * DIMc + d];             // [b,r,idx,d]
        si += pair[(((size_t)b * Lc + idx) * Lc + rl) * DIMc + d];  // [b,idx,r,d]
    }
    sm[0][h][d] = so;
    sm[1][h][d] = si;
    __syncthreads();
    if (h == 0) {
        g_out_mean[rr * DIMc + d] = (sm[0][0][d] + sm[0][1][d]) * (1.f / Kc);
        g_in_mean [rr * DIMc + d] = (sm[1][0][d] + sm[1][1][d]) * (1.f / Kc);
    }
}

// ---------------------------------------------------------------------------
// Kernel 2: agg GEMVs + gate GEMVs chained through smem.
// ---------------------------------------------------------------------------
__global__ void __launch_bounds__(256) agg_gate_kernel(
    const float* __restrict__ W_out, const float* __restrict__ b_out,
    const float* __restrict__ W_in,  const float* __restrict__ b_in,
    const float* __restrict__ W_g,   const float* __restrict__ b_g)
{
    __shared__ float s_om[RPB][DIMc];
    __shared__ float s_im[RPB][DIMc];
    __shared__ float s_a [2][RPB][DIMc];   // [0]=oa, [1]=ia

    const int t  = threadIdx.x;
    const int d  = t & 127;
    const int h  = t >> 7;
    const int r0 = blockIdx.x * RPB;

    for (int s = t; s < RPB * DIMc; s += 256) {
        const int r = s >> 7, dd = s & 127;
        s_om[r][dd] = g_out_mean[(r0 + r) * DIMc + dd];
        s_im[r][dd] = g_in_mean [(r0 + r) * DIMc + dd];
    }
    __syncthreads();

    {
        const float* __restrict__ W = h ? W_in : W_out;
        const float (*src)[DIMc]    = h ? s_im : s_om;
        float* __restrict__ dst     = h ? g_in_agg : g_out_agg;
        float acc[RPB];
        const float bv = h ? b_in[d] : b_out[d];
        #pragma unroll
        for (int r = 0; r < RPB; r++) acc[r] = bv;
        #pragma unroll 8
        for (int m = 0; m < DIMc; m++) {
            const float w = W[m * DIMc + d];
            #pragma unroll
            for (int r = 0; r < RPB; r++)
                acc[r] = fmaf(src[r][m], w, acc[r]);
        }
        #pragma unroll
        for (int r = 0; r < RPB; r++) {
            dst[(r0 + r) * DIMc + d] = acc[r];
            s_a[h][r][d] = acc[r];
        }
    }
    __syncthreads();

    {
        const float* __restrict__ W = W_g + h * DIMc * DIMc;
        float* __restrict__ dst     = h ? g_gi : g_go;
        float acc[RPB];
        const float bv = h ? 0.f : b_g[d];
        #pragma unroll
        for (int r = 0; r < RPB; r++) acc[r] = bv;
        #pragma unroll 8
        for (int m = 0; m < DIMc; m++) {
            const float w = W[m * DIMc + d];
            #pragma unroll
            for (int r = 0; r < RPB; r++)
                acc[r] = fmaf(s_a[h][r][m], w, acc[r]);
        }
        #pragma unroll
        for (int r = 0; r < RPB; r++)
            dst[(r0 + r) * DIMc + d] = acc[r];
    }
}

// ---------------------------------------------------------------------------
// Kernel 3: fused gate/blend + LayerNorm  [R7 structure + fp16 j-tiles].
// 16 lanes per row (8 floats/lane), one i-row per warp (oa/go in regs),
// ia/gi from smem as fp16 (one 16B LDS per array per lane per 2 rows).
// ---------------------------------------------------------------------------
__device__ __forceinline__ void blend4(
    const float4 p, const float4 OA, const float4 IA,
    const float4 GO, const float4 GI, float* x)
{
    float z, g, u;
    z = GO.x + GI.x; g = fmaf(0.5f, tanh_approx(0.5f * z), 0.5f);
    u = OA.x + IA.x; x[0] = fmaf(g, u - p.x, p.x);
    z = GO.y + GI.y; g = fmaf(0.5f, tanh_approx(0.5f * z), 0.5f);
    u = OA.y + IA.y; x[1] = fmaf(g, u - p.y, p.y);
    z = GO.z + GI.z; g = fmaf(0.5f, tanh_approx(0.5f * z), 0.5f);
    u = OA.z + IA.z; x[2] = fmaf(g, u - p.z, p.z);
    z = GO.w + GI.w; g = fmaf(0.5f, tanh_approx(0.5f * z), 0.5f);
    u = OA.w + IA.w; x[3] = fmaf(g, u - p.w, p.w);
}

__device__ __forceinline__ void ln_write(
    const float* x, const float4 lw0, const float4 lw1,
    const float4 lb0, const float4 lb1, float4* dst)
{
    float s = 0.f, sq = 0.f;
    #pragma unroll
    for (int e = 0; e < 8; e++) { s += x[e]; sq = fmaf(x[e], x[e], sq); }
    #pragma unroll
    for (int o = 8; o; o >>= 1) {
        s  += __shfl_xor_sync(0xFFFFFFFFu, s,  o);
        sq += __shfl_xor_sync(0xFFFFFFFFu, sq, o);
    }
    const float mean = s * (1.f / DIMc);
    const float rstd = rsqrtf(sq * (1.f / DIMc) - mean * mean + EPSc);
    float4 o0, o1;
    o0.x = fmaf((x[0] - mean) * rstd, lw0.x, lb0.x);
    o0.y = fmaf((x[1] - mean) * rstd, lw0.y, lb0.y);
    o0.z = fmaf((x[2] - mean) * rstd, lw0.z, lb0.z);
    o0.w = fmaf((x[3] - mean) * rstd, lw0.w, lb0.w);
    o1.x = fmaf((x[4] - mean) * rstd, lw1.x, lb1.x);
    o1.y = fmaf((x[5] - mean) * rstd, lw1.y, lb1.y);
    o1.z = fmaf((x[6] - mean) * rstd, lw1.z, lb1.z);
    o1.w = fmaf((x[7] - mean) * rstd, lw1.w, lb1.w);
    __stcs(&dst[0], o0);
    __stcs(&dst[1], o1);
}

// unpack a uint4 of 8 halves into two float4s
__device__ __forceinline__ void unpack8h(const uint4 v, float4& a, float4& b) {
    const __half2* h = (const __half2*)&v;
    const float2 f0 = __half22float2(h[0]);
    const float2 f1 = __half22float2(h[1]);
    const float2 f2 = __half22float2(h[2]);
    const float2 f3 = __half22float2(h[3]);
    a.x = f0.x; a.y = f0.y; a.z = f1.x; a.w = f1.y;
    b.x = f2.x; b.y = f2.y; b.z = f3.x; b.w = f3.y;
}

__global__ void __launch_bounds__(256) fuse_ln_kernel(
    const float* __restrict__ pair,
    const float* __restrict__ ln_w,
    const float* __restrict__ ln_b,
    float* __restrict__ out)
{
    __shared__ uint4 s_ia[FTJ][16];   // fp16: 16 chunks of 8 halves per row
    __shared__ uint4 s_gi[FTJ][16];

    const int t    = threadIdx.x;
    const int tile = blockIdx.x;             // b*(64*16) + it*16 + jt
    const int b    = tile >> 10;
    const int it   = (tile >> 4) & 63;
    const int jt   = tile & 15;
    const int i0   = it * FTI, j0 = jt * FTJ;

    const float4* __restrict__ ia4 = (const float4*)g_in_agg;
    const float4* __restrict__ gi4 = (const float4*)g_gi;

    // fill fp16 tiles: each thread converts 8 floats per iteration
    #pragma unroll
    for (int s = t; s < FTJ * 16; s += 256) {
        const int row = s >> 4, c = s & 15;
        const int gr = (b * Lc + j0 + row) * 32 + c * 2;
        const float4 a0 = ia4[gr], a1 = ia4[gr + 1];
        const float4 b0 = gi4[gr], b1 = gi4[gr + 1];
        uint4 va, vb;
        __half2* ha = (__half2*)&va;
        __half2* hb = (__half2*)&vb;
        ha[0] = __floats2half2_rn(a0.x, a0.y);
        ha[1] = __floats2half2_rn(a0.z, a0.w);
        ha[2] = __floats2half2_rn(a1.x, a1.y);
        ha[3] = __floats2half2_rn(a1.z, a1.w);
        hb[0] = __floats2half2_rn(b0.x, b0.y);
        hb[1] = __floats2half2_rn(b0.z, b0.w);
        hb[2] = __floats2half2_rn(b1.x, b1.y);
        hb[3] = __floats2half2_rn(b1.z, b1.w);
        s_ia[row][c] = va;
        s_gi[row][c] = vb;
    }
    __syncthreads();

    const int warp = t >> 5;
    const int lane = t & 31;
    const int grp  = lane >> 4;   // which j of the pair this lane serves
    const int lr   = lane & 15;   // 16-lane position within a row (8 floats)
    const int bi   = b * Lc + i0 + warp;

    const float4* __restrict__ oa4 = (const float4*)g_out_agg;
    const float4* __restrict__ go4 = (const float4*)g_go;
    const float4 oa0 = oa4[bi * 32 + lr * 2];
    const float4 oa1 = oa4[bi * 32 + lr * 2 + 1];
    const float4 go0 = go4[bi * 32 + lr * 2];
    const float4 go1 = go4[bi * 32 + lr * 2 + 1];
    const float4 lw0 = ((const float4*)ln_w)[lr * 2];
    const float4 lw1 = ((const float4*)ln_w)[lr * 2 + 1];
    const float4 lb0 = ((const float4*)ln_b)[lr * 2];
    const float4 lb1 = ((const float4*)ln_b)[lr * 2 + 1];

    const float4* __restrict__ p4 = (const float4*)pair;
    float4* __restrict__ o4p = (float4*)out;
    const size_t base = ((size_t)bi * Lc + j0) * 32 + lr * 2;

    #pragma unroll 1
    for (int jj = 0; jj < FTJ; jj += 4) {
        const int jA = jj + grp;          // rows {jj, jj+1} across the warp
        const int jB = jj + 2 + grp;      // rows {jj+2, jj+3}
        const size_t offA = base + (size_t)jA * 32;
        const size_t offB = base + (size_t)jB * 32;

        const float4 pA0 = __ldcs(&p4[offA]);
        const float4 pA1 = __ldcs(&p4[offA + 1]);
        const float4 pB0 = __ldcs(&p4[offB]);
        const float4 pB1 = __ldcs(&p4[offB + 1]);
        const uint4 viA = s_ia[jA][lr];
        const uint4 vgA = s_gi[jA][lr];
        const uint4 viB = s_ia[jB][lr];
        const uint4 vgB = s_gi[jB][lr];

        // --- rows A (jj, jj+1) ---
        {
            float4 ia0, ia1, gi0, gi1;
            unpack8h(viA, ia0, ia1);
            unpack8h(vgA, gi0, gi1);
            float x[8];
            blend4(pA0, oa0, ia0, go0, gi0, x);
            blend4(pA1, oa1, ia1, go1, gi1, x + 4);
            ln_write(x, lw0, lw1, lb0, lb1, &o4p[offA]);
        }
        // --- rows B (jj+2, jj+3) ---
        {
            float4 ia0, ia1, gi0, gi1;
            unpack8h(viB, ia0, ia1);
            unpack8h(vgB, gi0, gi1);
            float x[8];
            blend4(pB0, oa0, ia0, go0, gi0, x);
            blend4(pB1, oa1, ia1, go1, gi1, x + 4);
            ln_write(x, lw0, lw1, lb0, lb1, &o4p[offB]);
        }
    }
}

extern "C" void kernel_launch(void* const* d_in, const int* in_sizes, int n_in,
                              void* d_out, int out_size) {
    const float* pair  = (const float*)d_in[0];
    const float* W_out = (const float*)d_in[1];
    const float* b_out = (const float*)d_in[2];
    const float* W_in  = (const float*)d_in[3];
    const float* b_in  = (const float*)d_in[4];
    const float* W_g   = (const float*)d_in[5];
    const float* b_g   = (const float*)d_in[6];
    const float* ln_w  = (const float*)d_in[7];
    const float* ln_b  = (const float*)d_in[8];
    float* out = (float*)d_out;

    means_kernel<<<Bc * Lc, 256>>>(pair);
    agg_gate_kernel<<<(Bc * Lc) / RPB, 256>>>(W_out, b_out, W_in, b_in, W_g, b_g);
    fuse_ln_kernel<<<Bc * (Lc / FTI) * (Lc / FTJ), 256>>>(pair, ln_w, ln_b, out);
}